// round 1
// baseline (speedup 1.0000x reference)
#include <cuda_runtime.h>
#include <math.h>

// Problem constants
#define BB 2
#define TT 4096
#define DM 1024
#define DI 2048
#define CCHUNK 256
#define NCHUNK 16
#define KSZ 5

// scalar slots: 0=W0 sumsq, 1=eta, 2=decay, 3/4=sumsq(G) per batch, 5/6=sumsq(dW') per batch
__device__ float g_scal[8];
__device__ float g_vu[BB * TT * DM];   // 32 MB
__device__ float g_zu[BB * TT * DI];   // 64 MB
__device__ float g_G[BB * DM * DI];    // 16 MB
__device__ float g_dW[BB * DM * DI];   // 16 MB

// ---------------------------------------------------------------- helpers
__device__ __forceinline__ float warpSum(float v) {
#pragma unroll
    for (int o = 16; o > 0; o >>= 1) v += __shfl_xor_sync(0xffffffffu, v, o);
    return v;
}

// one use per kernel (no reuse hazard); blockDim.x == 256 everywhere it is used
__device__ __forceinline__ float blockSum(float v) {
    __shared__ float red[32];
    int lane = threadIdx.x & 31, w = threadIdx.x >> 5;
    v = warpSum(v);
    if (lane == 0) red[w] = v;
    __syncthreads();
    float r = (threadIdx.x < (blockDim.x >> 5)) ? red[threadIdx.x] : 0.0f;
    if (w == 0) {
        r = warpSum(r);
        if (lane == 0) red[0] = r;
    }
    __syncthreads();
    return red[0];
}

// packed fp32x2 FMA (Blackwell FFMA2 — only reachable via PTX)
__device__ __forceinline__ unsigned long long pk2(float x, float y) {
    unsigned long long r;
    asm("mov.b64 %0, {%1, %2};" : "=l"(r) : "f"(x), "f"(y));
    return r;
}
__device__ __forceinline__ void fma2(unsigned long long& d, unsigned long long a,
                                     unsigned long long b) {
    asm("fma.rn.f32x2 %0, %1, %2, %0;" : "+l"(d) : "l"(a), "l"(b));
}
__device__ __forceinline__ float2 upk2(unsigned long long v) {
    float f0, f1;
    asm("mov.b64 {%0, %1}, %2;" : "=f"(f0), "=f"(f1) : "l"(v));
    return make_float2(f0, f1);
}

// 16-deep K microloop on a 64x64 tile; a-operand broadcast, b-operand packed pairs
__device__ __forceinline__ void mma16(const float* __restrict__ A, int astr,
                                      const float* __restrict__ Bm, int bstr, int ty4,
                                      int tx4, unsigned long long acc[4][2]) {
#pragma unroll
    for (int k = 0; k < 16; k++) {
        float4 a = *(const float4*)(A + k * astr + ty4);
        ulonglong2 bp = *(const ulonglong2*)(Bm + k * bstr + tx4);
        unsigned long long a0 = pk2(a.x, a.x), a1 = pk2(a.y, a.y);
        unsigned long long a2 = pk2(a.z, a.z), a3 = pk2(a.w, a.w);
        fma2(acc[0][0], a0, bp.x); fma2(acc[0][1], a0, bp.y);
        fma2(acc[1][0], a1, bp.x); fma2(acc[1][1], a1, bp.y);
        fma2(acc[2][0], a2, bp.x); fma2(acc[2][1], a2, bp.y);
        fma2(acc[3][0], a3, bp.x); fma2(acc[3][1], a3, bp.y);
    }
}

// ---------------------------------------------------------------- init / prep
__global__ void k_init() {
    int i = blockIdx.x * blockDim.x + threadIdx.x;
    int stride = gridDim.x * blockDim.x;
    for (int j = i; j < BB * DM * DI; j += stride) g_dW[j] = 0.0f;
    if (blockIdx.x == 0 && threadIdx.x < 8) g_scal[threadIdx.x] = 0.0f;
}

__global__ void k_prep(const float* __restrict__ W0, const float* __restrict__ lil,
                       const float* __restrict__ ldl) {
    int i = blockIdx.x * blockDim.x + threadIdx.x;  // covers DM*DI/4 float4s exactly
    float4 w = ((const float4*)W0)[i];
    float s = w.x * w.x + w.y * w.y + w.z * w.z + w.w * w.w;
    s = blockSum(s);
    if (threadIdx.x == 0) atomicAdd(&g_scal[0], s);
    if (blockIdx.x == 0 && threadIdx.x == 0) {
        g_scal[1] = expf(lil[0]);
        float sg = 1.0f / (1.0f + expf(-ldl[0]));
        g_scal[2] = 0.9f + (0.995f - 0.9f) * sg;
    }
}

// causal depthwise conv + double rmsnorm -> vu   (one block per (b,t), 256 thr x 4 ch)
__global__ void k_vu(const float* __restrict__ src, const float* __restrict__ cw) {
    int b = blockIdx.x >> 12;
    int t = blockIdx.x & (TT - 1);
    int c0 = threadIdx.x << 2;
    float a0 = 0.f, a1 = 0.f, a2 = 0.f, a3 = 0.f;
#pragma unroll
    for (int j = 0; j < KSZ; j++) {
        int tj = t - (KSZ - 1) + j;
        if (tj >= 0) {
            float4 x = *(const float4*)(src + ((size_t)(b * TT + tj)) * DM + c0);
            a0 = fmaf(x.x, cw[(c0 + 0) * KSZ + j], a0);
            a1 = fmaf(x.y, cw[(c0 + 1) * KSZ + j], a1);
            a2 = fmaf(x.z, cw[(c0 + 2) * KSZ + j], a2);
            a3 = fmaf(x.w, cw[(c0 + 3) * KSZ + j], a3);
        }
    }
    float s = blockSum(a0 * a0 + a1 * a1 + a2 * a2 + a3 * a3);
    float ms = s * (1.0f / DM);
    float r1 = rsqrtf(ms + 1e-6f);
    float ms2 = ms / (ms + 1e-6f);       // mean(vhat^2) analytically
    float r = r1 * rsqrtf(ms2 + 1e-6f);  // combined double rms-norm factor
    *(float4*)(g_vu + ((size_t)(b * TT + t)) * DM + c0) =
        make_float4(a0 * r, a1 * r, a2 * r, a3 * r);
}

// rmsnorm(z) -> zu   (one block per (b,t), 256 thr x 8 elems)
__global__ void k_zu(const float* __restrict__ z) {
    size_t row = (size_t)blockIdx.x * DI;
    const float4* zr = (const float4*)(z + row);
    float4 a = zr[threadIdx.x];
    float4 c = zr[threadIdx.x + 256];
    float s = a.x * a.x + a.y * a.y + a.z * a.z + a.w * a.w + c.x * c.x + c.y * c.y +
              c.z * c.z + c.w * c.w;
    s = blockSum(s);
    float r = rsqrtf(s * (1.0f / DI) + 1e-6f);
    float4* o = (float4*)(g_zu + row);
    o[threadIdx.x] = make_float4(a.x * r, a.y * r, a.z * r, a.w * r);
    o[threadIdx.x + 256] = make_float4(c.x * r, c.y * r, c.z * r, c.w * r);
}

// ---------------------------------------------------------------- GEMM O
// o[b, t, o] = sum_d z[b,t,d] * (W0[o,d] + dW[b,o,d]) + bias[o]
// NT layout (both K-contiguous): transposing smem stores, double-buffered.
#define OST 68
__global__ __launch_bounds__(256) void k_gemmO(const float* __restrict__ z,
                                               const float* __restrict__ W0,
                                               const float* __restrict__ bias,
                                               float* __restrict__ out, int chunk) {
    __shared__ __align__(16) float As[2][16][OST];
    __shared__ __align__(16) float Bs[2][16][OST];
    const int b = blockIdx.z;
    const int m0 = blockIdx.x * 64;  // t within chunk
    const int n0 = blockIdx.y * 64;  // o
    const int tid = threadIdx.x;
    const int tx = tid & 15, ty = tid >> 4;
    const int lm = tid >> 2;
    const int lk = (tid & 3) << 2;

    const float* zrow = z + ((size_t)(b * TT + chunk * CCHUNK + m0 + lm)) * DI + lk;
    const float* wrow = W0 + (size_t)(n0 + lm) * DI + lk;
    const float* dwrow = g_dW + (size_t)b * DM * DI + (size_t)(n0 + lm) * DI + lk;

    unsigned long long acc[4][2];
#pragma unroll
    for (int i = 0; i < 4; i++) { acc[i][0] = 0ull; acc[i][1] = 0ull; }

    float4 av = *(const float4*)(zrow);
    float4 w1 = *(const float4*)(wrow);
    float4 w2 = *(const float4*)(dwrow);
    As[0][lk + 0][lm] = av.x; As[0][lk + 1][lm] = av.y;
    As[0][lk + 2][lm] = av.z; As[0][lk + 3][lm] = av.w;
    Bs[0][lk + 0][lm] = w1.x + w2.x; Bs[0][lk + 1][lm] = w1.y + w2.y;
    Bs[0][lk + 2][lm] = w1.z + w2.z; Bs[0][lk + 3][lm] = w1.w + w2.w;
    __syncthreads();

    int buf = 0;
    for (int kk = 16; kk < DI; kk += 16) {
        float4 nav = *(const float4*)(zrow + kk);
        float4 nw1 = *(const float4*)(wrow + kk);
        float4 nw2 = *(const float4*)(dwrow + kk);
        mma16(&As[buf][0][0], OST, &Bs[buf][0][0], OST, ty << 2, tx << 2, acc);
        int nb = buf ^ 1;
        As[nb][lk + 0][lm] = nav.x; As[nb][lk + 1][lm] = nav.y;
        As[nb][lk + 2][lm] = nav.z; As[nb][lk + 3][lm] = nav.w;
        Bs[nb][lk + 0][lm] = nw1.x + nw2.x; Bs[nb][lk + 1][lm] = nw1.y + nw2.y;
        Bs[nb][lk + 2][lm] = nw1.z + nw2.z; Bs[nb][lk + 3][lm] = nw1.w + nw2.w;
        __syncthreads();
        buf = nb;
    }
    mma16(&As[buf][0][0], OST, &Bs[buf][0][0], OST, ty << 2, tx << 2, acc);

    float4 bv = *(const float4*)&bias[n0 + (tx << 2)];
    float* ob = out + ((size_t)(b * TT + chunk * CCHUNK + m0 + (ty << 2))) * DM + n0 +
                (tx << 2);
#pragma unroll
    for (int im = 0; im < 4; im++) {
        float2 lo = upk2(acc[im][0]);
        float2 hi = upk2(acc[im][1]);
        *(float4*)(ob + (size_t)im * DM) =
            make_float4(lo.x + bv.x, lo.y + bv.y, hi.x + bv.z, hi.y + bv.w);
    }
    // zero the G sumsq accumulators for the G-GEMM that follows this chunk
    if (blockIdx.x == 0 && blockIdx.y == 0 && blockIdx.z == 0 && tid < 2)
        g_scal[3 + tid] = 0.0f;
}

// ---------------------------------------------------------------- GEMM G
// G[b,o,d] = (1/C) sum_t vu[b,t,o] * zu[b,t,d]   (TN layout: direct smem loads)
__global__ __launch_bounds__(256) void k_gemmG(int chunk) {
    __shared__ __align__(16) float As[2][16][64];
    __shared__ __align__(16) float Bs[2][16][64];
    const int b = blockIdx.z;
    const int m0 = blockIdx.x * 64;  // o
    const int n0 = blockIdx.y * 64;  // d
    const int tid = threadIdx.x;
    const int tx = tid & 15, ty = tid >> 4;
    const int lr = tid >> 4;
    const int lc = (tid & 15) << 2;

    const float* va = g_vu + ((size_t)(b * TT + chunk * CCHUNK)) * DM + m0 + lc;
    const float* zb = g_zu + ((size_t)(b * TT + chunk * CCHUNK)) * DI + n0 + lc;

    unsigned long long acc[4][2];
#pragma unroll
    for (int i = 0; i < 4; i++) { acc[i][0] = 0ull; acc[i][1] = 0ull; }

    *(float4*)&As[0][lr][lc] = *(const float4*)(va + (size_t)lr * DM);
    *(float4*)&Bs[0][lr][lc] = *(const float4*)(zb + (size_t)lr * DI);
    __syncthreads();

    int buf = 0;
    for (int kk = 16; kk < CCHUNK; kk += 16) {
        float4 na = *(const float4*)(va + (size_t)(kk + lr) * DM);
        float4 nb4 = *(const float4*)(zb + (size_t)(kk + lr) * DI);
        mma16(&As[buf][0][0], 64, &Bs[buf][0][0], 64, ty << 2, tx << 2, acc);
        int nb = buf ^ 1;
        *(float4*)&As[nb][lr][lc] = na;
        *(float4*)&Bs[nb][lr][lc] = nb4;
        __syncthreads();
        buf = nb;
    }
    mma16(&As[buf][0][0], 64, &Bs[buf][0][0], 64, ty << 2, tx << 2, acc);

    const float invC = 1.0f / CCHUNK;
    float ss = 0.0f;
    float* gb = g_G + (size_t)b * DM * DI;
#pragma unroll
    for (int im = 0; im < 4; im++) {
        float2 lo = upk2(acc[im][0]);
        float2 hi = upk2(acc[im][1]);
        float4 r = make_float4(lo.x * invC, lo.y * invC, hi.x * invC, hi.y * invC);
        ss += r.x * r.x + r.y * r.y + r.z * r.z + r.w * r.w;
        *(float4*)&gb[(size_t)(m0 + (ty << 2) + im) * DI + n0 + (tx << 2)] = r;
    }
    ss = blockSum(ss);
    if (threadIdx.x == 0) atomicAdd(&g_scal[3 + b], ss);
    // zero the dW sumsq accumulators for the update kernel that follows
    if (blockIdx.x == 0 && blockIdx.y == 0 && blockIdx.z == 0 && tid < 2)
        g_scal[5 + tid] = 0.0f;
}

// ---------------------------------------------------------------- dW update (projected G -> EMA) + sumsq(dW')
__global__ void k_update() {
    int b = blockIdx.y;
    size_t base = (size_t)b * (DM * DI / 4) + (size_t)blockIdx.x * 256 + threadIdx.x;
    float decay = g_scal[2];
    float eta = g_scal[1];
    float w0n = sqrtf(g_scal[0]);
    float sG = fminf(0.02f * w0n / (sqrtf(g_scal[3 + b]) + 1e-8f), 1.0f);
    float c = (1.0f - decay) * eta * sG;
    float4 g = ((const float4*)g_G)[base];
    float4 dw = ((const float4*)g_dW)[base];
    float4 nd = make_float4(decay * dw.x + c * g.x, decay * dw.y + c * g.y,
                            decay * dw.z + c * g.z, decay * dw.w + c * g.w);
    ((float4*)g_dW)[base] = nd;
    float ss = nd.x * nd.x + nd.y * nd.y + nd.z * nd.z + nd.w * nd.w;
    ss = blockSum(ss);
    if (threadIdx.x == 0) atomicAdd(&g_scal[5 + b], ss);
}

// ---------------------------------------------------------------- final dW projection (+ optional external write on last chunk)
__global__ void k_scaledw(float* __restrict__ dst) {
    int b = blockIdx.y;
    size_t base = (size_t)b * (DM * DI / 4) + (size_t)blockIdx.x * 256 + threadIdx.x;
    float w0n = sqrtf(g_scal[0]);
    float s = fminf(0.1f * w0n / (sqrtf(g_scal[5 + b]) + 1e-8f), 1.0f);
    float4 v = ((float4*)g_dW)[base];
    v.x *= s; v.y *= s; v.z *= s; v.w *= s;
    ((float4*)g_dW)[base] = v;
    if (dst) ((float4*)dst)[base] = v;
}

// ---------------------------------------------------------------- launch
extern "C" void kernel_launch(void* const* d_in, const int* in_sizes, int n_in,
                              void* d_out, int out_size) {
    const float* z = (const float*)d_in[0];
    const float* src = (const float*)d_in[1];
    const float* W0 = (const float*)d_in[2];
    const float* bias = (const float*)d_in[3];
    const float* cw = (const float*)d_in[4];
    const float* lil = (const float*)d_in[5];
    const float* ldl = (const float*)d_in[6];
    float* out = (float*)d_out;

    k_init<<<2048, 256>>>();
    k_prep<<<2048, 256>>>(W0, lil, ldl);
    k_vu<<<BB * TT, 256>>>(src, cw);
    k_zu<<<BB * TT, 256>>>(z);

    dim3 gO(CCHUNK / 64, DM / 64, BB);   // 4 x 16 x 2 = 128 blocks
    dim3 gG(DM / 64, DI / 64, BB);       // 16 x 32 x 2 = 1024 blocks
    dim3 gE(2048, BB);

    float* dwout = nullptr;
    if (out_size >= BB * TT * DM + BB * DM * DI) dwout = out + (size_t)BB * TT * DM;

    for (int c = 0; c < NCHUNK; c++) {
        k_gemmO<<<gO, 256>>>(z, W0, bias, out, c);
        k_gemmG<<<gG, 256>>>(c);
        k_update<<<gE, 256>>>();
        k_scaledw<<<gE, 256>>>(c == NCHUNK - 1 ? dwout : nullptr);
    }
}

// round 5
// speedup vs baseline: 1.0971x; 1.0971x over previous
#include <cuda_runtime.h>
#include <math.h>

// Problem constants
#define BB 2
#define TT 4096
#define DM 1024
#define DI 2048
#define CCHUNK 256
#define NCHUNK 16
#define KSZ 5

// scalar slots:
// 0 = W0 sumsq, 1 = eta, 2 = decay, 3/4 = sumsq(G) per batch,
// 5..8 = sumsq(dW_phys) per batch, parity ping-pong: slot(c,b) = 5 + (c&1)*2 + b
__device__ float g_scal[12];
__device__ float g_vu[BB * TT * DM];    // 32 MB
__device__ float g_zu[BB * TT * DI];    // 64 MB
__device__ float g_G[BB * DM * DI];     // 16 MB
__device__ float g_dW[BB * DM * DI];    // 16 MB (unprojected; scale tracked in g_scal)
__device__ float g_part[2][BB * CCHUNK * DM];  // split-K partials for gemmO

// ---------------------------------------------------------------- helpers
__device__ __forceinline__ float warpSum(float v) {
#pragma unroll
    for (int o = 16; o > 0; o >>= 1) v += __shfl_xor_sync(0xffffffffu, v, o);
    return v;
}

__device__ __forceinline__ float blockSum(float v) {
    __shared__ float red[32];
    int lane = threadIdx.x & 31, w = threadIdx.x >> 5;
    v = warpSum(v);
    if (lane == 0) red[w] = v;
    __syncthreads();
    float r = (threadIdx.x < (blockDim.x >> 5)) ? red[threadIdx.x] : 0.0f;
    if (w == 0) {
        r = warpSum(r);
        if (lane == 0) red[0] = r;
    }
    __syncthreads();
    return red[0];
}

// packed fp32x2 FMA (Blackwell FFMA2 — only via PTX)
__device__ __forceinline__ void fma2(unsigned long long& d, unsigned long long a,
                                     unsigned long long b) {
    asm("fma.rn.f32x2 %0, %1, %2, %0;" : "+l"(d) : "l"(a), "l"(b));
}
__device__ __forceinline__ float2 upk2(unsigned long long v) {
    float f0, f1;
    asm("mov.b64 {%0, %1}, %2;" : "=f"(f0), "=f"(f1) : "l"(v));
    return make_float2(f0, f1);
}

// derived dW projection scale from a sumsq slot
__device__ __forceinline__ float dw_scale(float w0n, float ss) {
    return fminf(0.1f * w0n / (sqrtf(ss) + 1e-8f), 1.0f);
}

// strides (floats) for smem tiles
#define ASTR 132   // duplicated-A rows: 128 payload floats + 4 pad
#define BSTRG 64   // gemmG B rows
#define BSTRO 68   // gemmO B rows (padded, scattered scalar stores)

// 16-deep K microloop, 64x64 tile, 4x4 micro-tile (n as 2 packed pairs).
// A is stored DUPLICATED: As[k][2*m+0]==As[k][2*m+1]==a[k][m]; reads are
// pre-packed pairs -> no MOVs. Per k: 3 LDS.128 + 8 FFMA2.
__device__ __forceinline__ void mma16(const float* __restrict__ A, int astr,
                                      const float* __restrict__ Bm, int bstr, int ty8,
                                      int tx4, unsigned long long acc[4][2]) {
#pragma unroll
    for (int k = 0; k < 16; k++) {
        ulonglong2 a01 = *(const ulonglong2*)(A + k * astr + ty8);
        ulonglong2 a23 = *(const ulonglong2*)(A + k * astr + ty8 + 4);
        ulonglong2 bp = *(const ulonglong2*)(Bm + k * bstr + tx4);
        fma2(acc[0][0], a01.x, bp.x); fma2(acc[0][1], a01.x, bp.y);
        fma2(acc[1][0], a01.y, bp.x); fma2(acc[1][1], a01.y, bp.y);
        fma2(acc[2][0], a23.x, bp.x); fma2(acc[2][1], a23.x, bp.y);
        fma2(acc[3][0], a23.y, bp.x); fma2(acc[3][1], a23.y, bp.y);
    }
}

// ---------------------------------------------------------------- init / prep
__global__ void k_init() {
    int i = blockIdx.x * blockDim.x + threadIdx.x;
    int stride = gridDim.x * blockDim.x;
    for (int j = i; j < BB * DM * DI; j += stride) g_dW[j] = 0.0f;
    if (blockIdx.x == 0 && threadIdx.x < 12) g_scal[threadIdx.x] = 0.0f;
}

__global__ void k_prep(const float* __restrict__ W0, const float* __restrict__ lil,
                       const float* __restrict__ ldl) {
    int i = blockIdx.x * blockDim.x + threadIdx.x;
    float4 w = ((const float4*)W0)[i];
    float s = w.x * w.x + w.y * w.y + w.z * w.z + w.w * w.w;
    s = blockSum(s);
    if (threadIdx.x == 0) atomicAdd(&g_scal[0], s);
    if (blockIdx.x == 0 && threadIdx.x == 0) {
        g_scal[1] = expf(lil[0]);
        float sg = 1.0f / (1.0f + expf(-ldl[0]));
        g_scal[2] = 0.9f + (0.995f - 0.9f) * sg;
    }
}

// causal depthwise conv + double rmsnorm -> vu
__global__ void k_vu(const float* __restrict__ src, const float* __restrict__ cw) {
    int b = blockIdx.x >> 12;
    int t = blockIdx.x & (TT - 1);
    int c0 = threadIdx.x << 2;
    float a0 = 0.f, a1 = 0.f, a2 = 0.f, a3 = 0.f;
#pragma unroll
    for (int j = 0; j < KSZ; j++) {
        int tj = t - (KSZ - 1) + j;
        if (tj >= 0) {
            float4 x = *(const float4*)(src + ((size_t)(b * TT + tj)) * DM + c0);
            a0 = fmaf(x.x, cw[(c0 + 0) * KSZ + j], a0);
            a1 = fmaf(x.y, cw[(c0 + 1) * KSZ + j], a1);
            a2 = fmaf(x.z, cw[(c0 + 2) * KSZ + j], a2);
            a3 = fmaf(x.w, cw[(c0 + 3) * KSZ + j], a3);
        }
    }
    float s = blockSum(a0 * a0 + a1 * a1 + a2 * a2 + a3 * a3);
    float ms = s * (1.0f / DM);
    float r1 = rsqrtf(ms + 1e-6f);
    float ms2 = ms / (ms + 1e-6f);
    float r = r1 * rsqrtf(ms2 + 1e-6f);
    *(float4*)(g_vu + ((size_t)(b * TT + t)) * DM + c0) =
        make_float4(a0 * r, a1 * r, a2 * r, a3 * r);
}

// rmsnorm(z) -> zu
__global__ void k_zu(const float* __restrict__ z) {
    size_t row = (size_t)blockIdx.x * DI;
    const float4* zr = (const float4*)(z + row);
    float4 a = zr[threadIdx.x];
    float4 c = zr[threadIdx.x + 256];
    float s = a.x * a.x + a.y * a.y + a.z * a.z + a.w * a.w + c.x * c.x + c.y * c.y +
              c.z * c.z + c.w * c.w;
    s = blockSum(s);
    float r = rsqrtf(s * (1.0f / DI) + 1e-6f);
    float4* o = (float4*)(g_zu + row);
    o[threadIdx.x] = make_float4(a.x * r, a.y * r, a.z * r, a.w * r);
    o[threadIdx.x + 256] = make_float4(c.x * r, c.y * r, c.z * r, c.w * r);
}

// ---------------------------------------------------------------- GEMM O (split-K=2)
// partial[h][b,t,o] = sum_{d in half h} z[b,t,d] * (W0[o,d] + s*dW[b,o,d])
__global__ __launch_bounds__(256) void k_gemmO(const float* __restrict__ z,
                                               const float* __restrict__ W0,
                                               int chunk) {
    __shared__ __align__(16) float As[2][16][ASTR];
    __shared__ __align__(16) float Bs[2][16][BSTRO];
    const int b = blockIdx.z >> 1;
    const int h = blockIdx.z & 1;
    const int m0 = blockIdx.x * 64;  // t within chunk
    const int n0 = blockIdx.y * 64;  // o
    const int tid = threadIdx.x;
    const int tx4 = (tid & 15) << 2;
    const int ty8 = (tid >> 4) << 3;
    const int lm = tid >> 2;
    const int lk = (tid & 3) << 2;
    const int kbase = h * (DI / 2);

    // dW scale from previous chunk's parity slot (zero-init -> s=1 for chunk 0)
    float w0n = sqrtf(g_scal[0]);
    float s = dw_scale(w0n, g_scal[5 + (((chunk - 1) & 1) << 1) + b]);

    const float* zrow =
        z + ((size_t)(b * TT + chunk * CCHUNK + m0 + lm)) * DI + kbase + lk;
    const float* wrow = W0 + (size_t)(n0 + lm) * DI + kbase + lk;
    const float* dwrow =
        g_dW + (size_t)b * DM * DI + (size_t)(n0 + lm) * DI + kbase + lk;

    unsigned long long acc[4][2];
#pragma unroll
    for (int i = 0; i < 4; i++) { acc[i][0] = 0ull; acc[i][1] = 0ull; }

    {
        float4 av = *(const float4*)(zrow);
        float4 w1 = *(const float4*)(wrow);
        float4 w2 = *(const float4*)(dwrow);
        *(float2*)&As[0][lk + 0][2 * lm] = make_float2(av.x, av.x);
        *(float2*)&As[0][lk + 1][2 * lm] = make_float2(av.y, av.y);
        *(float2*)&As[0][lk + 2][2 * lm] = make_float2(av.z, av.z);
        *(float2*)&As[0][lk + 3][2 * lm] = make_float2(av.w, av.w);
        Bs[0][lk + 0][lm] = fmaf(s, w2.x, w1.x);
        Bs[0][lk + 1][lm] = fmaf(s, w2.y, w1.y);
        Bs[0][lk + 2][lm] = fmaf(s, w2.z, w1.z);
        Bs[0][lk + 3][lm] = fmaf(s, w2.w, w1.w);
    }
    __syncthreads();

    int buf = 0;
    for (int kk = 16; kk < DI / 2; kk += 16) {
        float4 av = *(const float4*)(zrow + kk);
        float4 w1 = *(const float4*)(wrow + kk);
        float4 w2 = *(const float4*)(dwrow + kk);
        mma16(&As[buf][0][0], ASTR, &Bs[buf][0][0], BSTRO, ty8, tx4, acc);
        int nb = buf ^ 1;
        *(float2*)&As[nb][lk + 0][2 * lm] = make_float2(av.x, av.x);
        *(float2*)&As[nb][lk + 1][2 * lm] = make_float2(av.y, av.y);
        *(float2*)&As[nb][lk + 2][2 * lm] = make_float2(av.z, av.z);
        *(float2*)&As[nb][lk + 3][2 * lm] = make_float2(av.w, av.w);
        Bs[nb][lk + 0][lm] = fmaf(s, w2.x, w1.x);
        Bs[nb][lk + 1][lm] = fmaf(s, w2.y, w1.y);
        Bs[nb][lk + 2][lm] = fmaf(s, w2.z, w1.z);
        Bs[nb][lk + 3][lm] = fmaf(s, w2.w, w1.w);
        __syncthreads();
        buf = nb;
    }
    mma16(&As[buf][0][0], ASTR, &Bs[buf][0][0], BSTRO, ty8, tx4, acc);

    float* ob = g_part[h] + ((size_t)b * CCHUNK + m0 + (ty8 >> 1)) * DM + n0 + tx4;
#pragma unroll
    for (int im = 0; im < 4; im++) {
        float2 lo = upk2(acc[im][0]);
        float2 hi = upk2(acc[im][1]);
        *(float4*)(ob + (size_t)im * DM) = make_float4(lo.x, lo.y, hi.x, hi.y);
    }
}

// combine split-K partials + bias -> out; also zero scalar accumulators for this chunk
__global__ void k_combine(const float* __restrict__ bias, float* __restrict__ out,
                          int chunk) {
    int i = blockIdx.x * blockDim.x + threadIdx.x;  // float4 index over BB*CCHUNK*DM
    float4 p0 = ((const float4*)g_part[0])[i];
    float4 p1 = ((const float4*)g_part[1])[i];
    int n0 = (i << 2) & (DM - 1);
    float4 bv = *(const float4*)&bias[n0];
    int elem = i << 2;
    int b = elem / (CCHUNK * DM);
    int r = elem - b * (CCHUNK * DM);
    float* dst = out + ((size_t)(b * TT + chunk * CCHUNK)) * DM + r;
    *(float4*)dst = make_float4(p0.x + p1.x + bv.x, p0.y + p1.y + bv.y,
                                p0.z + p1.z + bv.z, p0.w + p1.w + bv.w);
    if (blockIdx.x == 0 && threadIdx.x < 4) {
        if (threadIdx.x < 2) g_scal[3 + threadIdx.x] = 0.0f;            // G sumsq
        else g_scal[5 + ((chunk & 1) << 1) + (threadIdx.x - 2)] = 0.0f; // dW sumsq slot(c)
    }
}

// ---------------------------------------------------------------- GEMM G
// G[b,o,d] = (1/C) sum_t vu[b,t,o] * zu[b,t,d]
__global__ __launch_bounds__(256) void k_gemmG(int chunk) {
    __shared__ __align__(16) float As[2][16][ASTR];
    __shared__ __align__(16) float Bs[2][16][BSTRG];
    const int b = blockIdx.z;
    const int m0 = blockIdx.x * 64;  // o
    const int n0 = blockIdx.y * 64;  // d
    const int tid = threadIdx.x;
    const int tx4 = (tid & 15) << 2;
    const int ty8 = (tid >> 4) << 3;
    const int lr = tid >> 4;
    const int lc = (tid & 15) << 2;

    const float* va = g_vu + ((size_t)(b * TT + chunk * CCHUNK)) * DM + m0 + lc;
    const float* zb = g_zu + ((size_t)(b * TT + chunk * CCHUNK)) * DI + n0 + lc;

    unsigned long long acc[4][2];
#pragma unroll
    for (int i = 0; i < 4; i++) { acc[i][0] = 0ull; acc[i][1] = 0ull; }

    {
        float4 v = *(const float4*)(va + (size_t)lr * DM);
        float4 u = *(const float4*)(zb + (size_t)lr * DI);
        *(float4*)&As[0][lr][2 * lc] = make_float4(v.x, v.x, v.y, v.y);
        *(float4*)&As[0][lr][2 * lc + 4] = make_float4(v.z, v.z, v.w, v.w);
        *(float4*)&Bs[0][lr][lc] = u;
    }
    __syncthreads();

    int buf = 0;
    for (int kk = 16; kk < CCHUNK; kk += 16) {
        float4 v = *(const float4*)(va + (size_t)(kk + lr) * DM);
        float4 u = *(const float4*)(zb + (size_t)(kk + lr) * DI);
        mma16(&As[buf][0][0], ASTR, &Bs[buf][0][0], BSTRG, ty8, tx4, acc);
        int nb = buf ^ 1;
        *(float4*)&As[nb][lr][2 * lc] = make_float4(v.x, v.x, v.y, v.y);
        *(float4*)&As[nb][lr][2 * lc + 4] = make_float4(v.z, v.z, v.w, v.w);
        *(float4*)&Bs[nb][lr][lc] = u;
        __syncthreads();
        buf = nb;
    }
    mma16(&As[buf][0][0], ASTR, &Bs[buf][0][0], BSTRG, ty8, tx4, acc);

    const float invC = 1.0f / CCHUNK;
    float ss = 0.0f;
    float* gb = g_G + (size_t)b * DM * DI;
#pragma unroll
    for (int im = 0; im < 4; im++) {
        float2 lo = upk2(acc[im][0]);
        float2 hi = upk2(acc[im][1]);
        float4 r = make_float4(lo.x * invC, lo.y * invC, hi.x * invC, hi.y * invC);
        ss += r.x * r.x + r.y * r.y + r.z * r.z + r.w * r.w;
        *(float4*)&gb[(size_t)(m0 + (ty8 >> 1) + im) * DI + n0 + tx4] = r;
    }
    ss = blockSum(ss);
    if (threadIdx.x == 0) atomicAdd(&g_scal[3 + b], ss);
}

// ---------------------------------------------------------------- dW EMA update
// dW_phys_new = decay * (s_prev * dW_phys) + (1-decay)*eta*sG * G ; accumulate sumsq
__global__ void k_update(int chunk) {
    int b = blockIdx.y;
    size_t base = (size_t)b * (DM * DI / 4) + (size_t)blockIdx.x * 256 + threadIdx.x;
    float decay = g_scal[2];
    float eta = g_scal[1];
    float w0n = sqrtf(g_scal[0]);
    float sG = fminf(0.02f * w0n / (sqrtf(g_scal[3 + b]) + 1e-8f), 1.0f);
    float s_prev = dw_scale(w0n, g_scal[5 + (((chunk - 1) & 1) << 1) + b]);
    float dk = decay * s_prev;
    float c = (1.0f - decay) * eta * sG;
    float4 g = ((const float4*)g_G)[base];
    float4 dw = ((const float4*)g_dW)[base];
    float4 nd = make_float4(dk * dw.x + c * g.x, dk * dw.y + c * g.y,
                            dk * dw.z + c * g.z, dk * dw.w + c * g.w);
    ((float4*)g_dW)[base] = nd;
    float ss = nd.x * nd.x + nd.y * nd.y + nd.z * nd.z + nd.w * nd.w;
    ss = blockSum(ss);
    if (threadIdx.x == 0) atomicAdd(&g_scal[5 + ((chunk & 1) << 1) + b], ss);
}

// ---------------------------------------------------------------- final projected dW write
__global__ void k_final(float* __restrict__ dst) {
    int b = blockIdx.y;
    size_t base = (size_t)b * (DM * DI / 4) + (size_t)blockIdx.x * 256 + threadIdx.x;
    float w0n = sqrtf(g_scal[0]);
    float s = dw_scale(w0n, g_scal[5 + (((NCHUNK - 1) & 1) << 1) + b]);
    float4 v = ((const float4*)g_dW)[base];
    ((float4*)dst)[base] = make_float4(v.x * s, v.y * s, v.z * s, v.w * s);
}

// ---------------------------------------------------------------- launch
extern "C" void kernel_launch(void* const* d_in, const int* in_sizes, int n_in,
                              void* d_out, int out_size) {
    const float* z = (const float*)d_in[0];
    const float* src = (const float*)d_in[1];
    const float* W0 = (const float*)d_in[2];
    const float* bias = (const float*)d_in[3];
    const float* cw = (const float*)d_in[4];
    const float* lil = (const float*)d_in[5];
    const float* ldl = (const float*)d_in[6];
    float* out = (float*)d_out;

    k_init<<<2048, 256>>>();
    k_prep<<<2048, 256>>>(W0, lil, ldl);
    k_vu<<<BB * TT, 256>>>(src, cw);
    k_zu<<<BB * TT, 256>>>(z);

    dim3 gO(CCHUNK / 64, DM / 64, BB * 2);  // 4 x 16 x 4 = 256 blocks (split-K=2)
    dim3 gG(DM / 64, DI / 64, BB);          // 16 x 32 x 2 = 1024 blocks
    dim3 gE(2048, BB);
    int nComb = BB * CCHUNK * DM / 4 / 256;  // 512 blocks

    for (int c = 0; c < NCHUNK; c++) {
        k_gemmO<<<gO, 256>>>(z, W0, c);
        k_combine<<<nComb, 256>>>(bias, out, c);
        k_gemmG<<<gG, 256>>>(c);
        k_update<<<gE, 256>>>(c);
    }

    if (out_size >= BB * TT * DM + BB * DM * DI) {
        float* dwout = out + (size_t)BB * TT * DM;
        k_final<<<gE, 256>>>(dwout);
    }
}

// round 8
// speedup vs baseline: 1.5515x; 1.4143x over previous
#include <cuda_runtime.h>
#include <math.h>

// Problem constants
#define BB 2
#define TT 4096
#define DM 1024
#define DI 2048
#define CCHUNK 256
#define NCHUNK 16
#define KSZ 5
#define SPLITK 8

// scalar slots:
// 0 = W0 sumsq, 1 = eta, 2 = decay, 3/4 = sumsq(G) per batch,
// 5..8 = sumsq(dW_phys) per batch, parity ping-pong: slot(c,b) = 5 + (c&1)*2 + b
__device__ float g_scal[12];
__device__ float g_vu[BB * TT * DM];    // 32 MB
__device__ float g_zu[BB * TT * DI];    // 64 MB
__device__ float g_G[BB * DM * DI];     // 16 MB
__device__ float g_dW[BB * DM * DI];    // 16 MB (unprojected; scale tracked in g_scal)
__device__ float g_part[SPLITK][BB * CCHUNK * DM];  // split-K partials for gemmO (64 MB)

// ---------------------------------------------------------------- helpers
__device__ __forceinline__ float warpSum(float v) {
#pragma unroll
    for (int o = 16; o > 0; o >>= 1) v += __shfl_xor_sync(0xffffffffu, v, o);
    return v;
}

__device__ __forceinline__ float blockSum(float v) {
    __shared__ float red[32];
    int lane = threadIdx.x & 31, w = threadIdx.x >> 5;
    v = warpSum(v);
    if (lane == 0) red[w] = v;
    __syncthreads();
    float r = (threadIdx.x < (blockDim.x >> 5)) ? red[threadIdx.x] : 0.0f;
    if (w == 0) {
        r = warpSum(r);
        if (lane == 0) red[0] = r;
    }
    __syncthreads();
    return red[0];
}

// packed fp32x2 FMA (Blackwell FFMA2 — only via PTX)
__device__ __forceinline__ void fma2(unsigned long long& d, unsigned long long a,
                                     unsigned long long b) {
    asm("fma.rn.f32x2 %0, %1, %2, %0;" : "+l"(d) : "l"(a), "l"(b));
}
__device__ __forceinline__ unsigned long long pk2(float x) {
    unsigned long long r;
    asm("mov.b64 %0, {%1, %1};" : "=l"(r) : "f"(x));
    return r;
}
__device__ __forceinline__ float2 upk2(unsigned long long v) {
    float f0, f1;
    asm("mov.b64 {%0, %1}, %2;" : "=f"(f0), "=f"(f1) : "l"(v));
    return make_float2(f0, f1);
}

// derived dW projection scale from a sumsq slot
__device__ __forceinline__ float dw_scale(float w0n, float ss) {
    return fminf(0.1f * w0n / (sqrtf(ss) + 1e-8f), 1.0f);
}

#define OAS 132  // gemmO smem stride (132*4B=528, 16 | 528 -> f4-aligned; conflict-free T-stores)
#define GAS 128  // gemmG smem stride

// NK-deep K microloop, 128x128 tile, 8x8 micro-tile.
// Per k: 2 LDS.128 A + 2 LDS.128 B (pre-packed n-pairs) + 8 MOV (alu) + 32 FFMA2.
// 64 B smem per 64 FMA = 1 B/FMA -> exactly at the 128B/cyc smem : 128FMA/cyc balance.
template <int NK, int AS, int BS>
__device__ __forceinline__ void mmaK(const float* __restrict__ A,
                                     const float* __restrict__ B, int ty8, int tx8,
                                     unsigned long long acc[8][4]) {
#pragma unroll
    for (int k = 0; k < NK; k++) {
        float4 a0 = *(const float4*)(A + k * AS + ty8);
        float4 a1 = *(const float4*)(A + k * AS + ty8 + 4);
        ulonglong2 b0 = *(const ulonglong2*)(B + k * BS + tx8);
        ulonglong2 b1 = *(const ulonglong2*)(B + k * BS + tx8 + 4);
        unsigned long long ap[8];
        ap[0] = pk2(a0.x); ap[1] = pk2(a0.y); ap[2] = pk2(a0.z); ap[3] = pk2(a0.w);
        ap[4] = pk2(a1.x); ap[5] = pk2(a1.y); ap[6] = pk2(a1.z); ap[7] = pk2(a1.w);
#pragma unroll
        for (int m = 0; m < 8; m++) {
            fma2(acc[m][0], ap[m], b0.x);
            fma2(acc[m][1], ap[m], b0.y);
            fma2(acc[m][2], ap[m], b1.x);
            fma2(acc[m][3], ap[m], b1.y);
        }
    }
}

// ---------------------------------------------------------------- init / prep
__global__ void k_init() {
    int i = blockIdx.x * blockDim.x + threadIdx.x;
    int stride = gridDim.x * blockDim.x;
    for (int j = i; j < BB * DM * DI; j += stride) g_dW[j] = 0.0f;
    if (blockIdx.x == 0 && threadIdx.x < 12) g_scal[threadIdx.x] = 0.0f;
}

__global__ void k_prep(const float* __restrict__ W0, const float* __restrict__ lil,
                       const float* __restrict__ ldl) {
    int i = blockIdx.x * blockDim.x + threadIdx.x;
    float4 w = ((const float4*)W0)[i];
    float s = w.x * w.x + w.y * w.y + w.z * w.z + w.w * w.w;
    s = blockSum(s);
    if (threadIdx.x == 0) atomicAdd(&g_scal[0], s);
    if (blockIdx.x == 0 && threadIdx.x == 0) {
        g_scal[1] = expf(lil[0]);
        float sg = 1.0f / (1.0f + expf(-ldl[0]));
        g_scal[2] = 0.9f + (0.995f - 0.9f) * sg;
    }
}

// causal depthwise conv + double rmsnorm -> vu
__global__ void k_vu(const float* __restrict__ src, const float* __restrict__ cw) {
    int b = blockIdx.x >> 12;
    int t = blockIdx.x & (TT - 1);
    int c0 = threadIdx.x << 2;
    float a0 = 0.f, a1 = 0.f, a2 = 0.f, a3 = 0.f;
#pragma unroll
    for (int j = 0; j < KSZ; j++) {
        int tj = t - (KSZ - 1) + j;
        if (tj >= 0) {
            float4 x = *(const float4*)(src + ((size_t)(b * TT + tj)) * DM + c0);
            a0 = fmaf(x.x, cw[(c0 + 0) * KSZ + j], a0);
            a1 = fmaf(x.y, cw[(c0 + 1) * KSZ + j], a1);
            a2 = fmaf(x.z, cw[(c0 + 2) * KSZ + j], a2);
            a3 = fmaf(x.w, cw[(c0 + 3) * KSZ + j], a3);
        }
    }
    float s = blockSum(a0 * a0 + a1 * a1 + a2 * a2 + a3 * a3);
    float ms = s * (1.0f / DM);
    float r1 = rsqrtf(ms + 1e-6f);
    float ms2 = ms / (ms + 1e-6f);
    float r = r1 * rsqrtf(ms2 + 1e-6f);
    *(float4*)(g_vu + ((size_t)(b * TT + t)) * DM + c0) =
        make_float4(a0 * r, a1 * r, a2 * r, a3 * r);
}

// rmsnorm(z) -> zu
__global__ void k_zu(const float* __restrict__ z) {
    size_t row = (size_t)blockIdx.x * DI;
    const float4* zr = (const float4*)(z + row);
    float4 a = zr[threadIdx.x];
    float4 c = zr[threadIdx.x + 256];
    float s = a.x * a.x + a.y * a.y + a.z * a.z + a.w * a.w + c.x * c.x + c.y * c.y +
              c.z * c.z + c.w * c.w;
    s = blockSum(s);
    float r = rsqrtf(s * (1.0f / DI) + 1e-6f);
    float4* o = (float4*)(g_zu + row);
    o[threadIdx.x] = make_float4(a.x * r, a.y * r, a.z * r, a.w * r);
    o[threadIdx.x + 256] = make_float4(c.x * r, c.y * r, c.z * r, c.w * r);
}

// ---------------------------------------------------------------- GEMM O (split-K=8)
// partial[h][b,t,o] = sum_{d in slice h} z[b,t,d] * (W0[o,d] + s*dW[b,o,d])
// 128x128 tile, BK=8, NT layout (transposing scalar stores, conflict-free @ OAS=132)
__global__ __launch_bounds__(256, 2) void k_gemmO(const float* __restrict__ z,
                                                  const float* __restrict__ W0,
                                                  int chunk) {
    __shared__ __align__(16) float As[2][8][OAS];
    __shared__ __align__(16) float Bs[2][8][OAS];
    const int b = blockIdx.z >> 3;
    const int h = blockIdx.z & 7;
    const int m0 = blockIdx.x * 128;  // t within chunk
    const int n0 = blockIdx.y * 128;  // o
    const int tid = threadIdx.x;
    const int tx8 = (tid & 15) << 3;
    const int ty8 = (tid >> 4) << 3;
    const int lm = tid >> 1;          // 0..127
    const int lk = (tid & 1) << 2;    // 0 or 4
    const int kbase = h * (DI / SPLITK);  // 256-wide K slice

    // dW scale from previous chunk's parity slot (zero-init -> s=1 for chunk 0)
    float w0n = sqrtf(g_scal[0]);
    float s = dw_scale(w0n, g_scal[5 + (((chunk - 1) & 1) << 1) + b]);

    const float* zrow =
        z + ((size_t)(b * TT + chunk * CCHUNK + m0 + lm)) * DI + kbase + lk;
    const float* wrow = W0 + (size_t)(n0 + lm) * DI + kbase + lk;
    const float* dwrow =
        g_dW + (size_t)b * DM * DI + (size_t)(n0 + lm) * DI + kbase + lk;

    unsigned long long acc[8][4];
#pragma unroll
    for (int i = 0; i < 8; i++)
#pragma unroll
        for (int j = 0; j < 4; j++) acc[i][j] = 0ull;

    {
        float4 av = *(const float4*)(zrow);
        float4 w1 = *(const float4*)(wrow);
        float4 w2 = *(const float4*)(dwrow);
        As[0][lk + 0][lm] = av.x; As[0][lk + 1][lm] = av.y;
        As[0][lk + 2][lm] = av.z; As[0][lk + 3][lm] = av.w;
        Bs[0][lk + 0][lm] = fmaf(s, w2.x, w1.x);
        Bs[0][lk + 1][lm] = fmaf(s, w2.y, w1.y);
        Bs[0][lk + 2][lm] = fmaf(s, w2.z, w1.z);
        Bs[0][lk + 3][lm] = fmaf(s, w2.w, w1.w);
    }
    __syncthreads();

    int buf = 0;
    for (int kk = 8; kk < DI / SPLITK; kk += 8) {
        float4 av = *(const float4*)(zrow + kk);
        float4 w1 = *(const float4*)(wrow + kk);
        float4 w2 = *(const float4*)(dwrow + kk);
        mmaK<8, OAS, OAS>(&As[buf][0][0], &Bs[buf][0][0], ty8, tx8, acc);
        int nb = buf ^ 1;
        As[nb][lk + 0][lm] = av.x; As[nb][lk + 1][lm] = av.y;
        As[nb][lk + 2][lm] = av.z; As[nb][lk + 3][lm] = av.w;
        Bs[nb][lk + 0][lm] = fmaf(s, w2.x, w1.x);
        Bs[nb][lk + 1][lm] = fmaf(s, w2.y, w1.y);
        Bs[nb][lk + 2][lm] = fmaf(s, w2.z, w1.z);
        Bs[nb][lk + 3][lm] = fmaf(s, w2.w, w1.w);
        __syncthreads();
        buf = nb;
    }
    mmaK<8, OAS, OAS>(&As[buf][0][0], &Bs[buf][0][0], ty8, tx8, acc);

    float* ob = g_part[h] + ((size_t)b * CCHUNK + m0 + ty8) * DM + n0 + tx8;
#pragma unroll
    for (int im = 0; im < 8; im++) {
        float2 r0 = upk2(acc[im][0]);
        float2 r1 = upk2(acc[im][1]);
        float2 r2 = upk2(acc[im][2]);
        float2 r3 = upk2(acc[im][3]);
        *(float4*)(ob + (size_t)im * DM) = make_float4(r0.x, r0.y, r1.x, r1.y);
        *(float4*)(ob + (size_t)im * DM + 4) = make_float4(r2.x, r2.y, r3.x, r3.y);
    }
}

// combine split-K partials + bias -> out; also zero scalar accumulators for this chunk
__global__ void k_combine(const float* __restrict__ bias, float* __restrict__ out,
                          int chunk) {
    int i = blockIdx.x * blockDim.x + threadIdx.x;  // float4 index over BB*CCHUNK*DM
    int n0 = (i << 2) & (DM - 1);
    float4 a = *(const float4*)&bias[n0];
#pragma unroll
    for (int hh = 0; hh < SPLITK; hh++) {
        float4 p = ((const float4*)g_part[hh])[i];
        a.x += p.x; a.y += p.y; a.z += p.z; a.w += p.w;
    }
    int elem = i << 2;
    int b = elem / (CCHUNK * DM);
    int r = elem - b * (CCHUNK * DM);
    float* dst = out + ((size_t)(b * TT + chunk * CCHUNK)) * DM + r;
    *(float4*)dst = a;
    if (blockIdx.x == 0 && threadIdx.x < 4) {
        if (threadIdx.x < 2) g_scal[3 + threadIdx.x] = 0.0f;            // G sumsq
        else g_scal[5 + ((chunk & 1) << 1) + (threadIdx.x - 2)] = 0.0f; // dW sumsq slot(c)
    }
}

// ---------------------------------------------------------------- GEMM G
// G[b,o,d] = (1/C) sum_t vu[b,t,o] * zu[b,t,d]   (TN: direct vectorized smem stores)
__global__ __launch_bounds__(256, 2) void k_gemmG(int chunk) {
    __shared__ __align__(16) float As[2][16][GAS];
    __shared__ __align__(16) float Bs[2][16][GAS];
    const int b = blockIdx.z;
    const int m0 = blockIdx.x * 128;  // o
    const int n0 = blockIdx.y * 128;  // d
    const int tid = threadIdx.x;
    const int tx8 = (tid & 15) << 3;
    const int ty8 = (tid >> 4) << 3;
    const int lr = tid >> 4;          // 0..15
    const int lc = (tid & 15) << 3;   // 0..120

    const float* va = g_vu + ((size_t)(b * TT + chunk * CCHUNK + lr)) * DM + m0 + lc;
    const float* zb = g_zu + ((size_t)(b * TT + chunk * CCHUNK + lr)) * DI + n0 + lc;

    unsigned long long acc[8][4];
#pragma unroll
    for (int i = 0; i < 8; i++)
#pragma unroll
        for (int j = 0; j < 4; j++) acc[i][j] = 0ull;

    {
        float4 v0 = *(const float4*)(va);
        float4 v1 = *(const float4*)(va + 4);
        float4 u0 = *(const float4*)(zb);
        float4 u1 = *(const float4*)(zb + 4);
        *(float4*)&As[0][lr][lc] = v0;
        *(float4*)&As[0][lr][lc + 4] = v1;
        *(float4*)&Bs[0][lr][lc] = u0;
        *(float4*)&Bs[0][lr][lc + 4] = u1;
    }
    __syncthreads();

    int buf = 0;
    for (int kk = 16; kk < CCHUNK; kk += 16) {
        float4 v0 = *(const float4*)(va + (size_t)kk * DM);
        float4 v1 = *(const float4*)(va + (size_t)kk * DM + 4);
        float4 u0 = *(const float4*)(zb + (size_t)kk * DI);
        float4 u1 = *(const float4*)(zb + (size_t)kk * DI + 4);
        mmaK<16, GAS, GAS>(&As[buf][0][0], &Bs[buf][0][0], ty8, tx8, acc);
        int nb = buf ^ 1;
        *(float4*)&As[nb][lr][lc] = v0;
        *(float4*)&As[nb][lr][lc + 4] = v1;
        *(float4*)&Bs[nb][lr][lc] = u0;
        *(float4*)&Bs[nb][lr][lc + 4] = u1;
        __syncthreads();
        buf = nb;
    }
    mmaK<16, GAS, GAS>(&As[buf][0][0], &Bs[buf][0][0], ty8, tx8, acc);

    const float invC = 1.0f / CCHUNK;
    float ss = 0.0f;
    float* gb = g_G + (size_t)b * DM * DI + (size_t)(m0 + ty8) * DI + n0 + tx8;
#pragma unroll
    for (int im = 0; im < 8; im++) {
        float2 r0 = upk2(acc[im][0]);
        float2 r1 = upk2(acc[im][1]);
        float2 r2 = upk2(acc[im][2]);
        float2 r3 = upk2(acc[im][3]);
        float4 lo = make_float4(r0.x * invC, r0.y * invC, r1.x * invC, r1.y * invC);
        float4 hi = make_float4(r2.x * invC, r2.y * invC, r3.x * invC, r3.y * invC);
        ss += lo.x * lo.x + lo.y * lo.y + lo.z * lo.z + lo.w * lo.w +
              hi.x * hi.x + hi.y * hi.y + hi.z * hi.z + hi.w * hi.w;
        *(float4*)(gb + (size_t)im * DI) = lo;
        *(float4*)(gb + (size_t)im * DI + 4) = hi;
    }
    ss = blockSum(ss);
    if (threadIdx.x == 0) atomicAdd(&g_scal[3 + b], ss);
}

// ---------------------------------------------------------------- dW EMA update
// dW_phys_new = decay * (s_prev * dW_phys) + (1-decay)*eta*sG * G ; accumulate sumsq
__global__ void k_update(int chunk) {
    int b = blockIdx.y;
    size_t base = (size_t)b * (DM * DI / 4) + (size_t)blockIdx.x * 256 + threadIdx.x;
    float decay = g_scal[2];
    float eta = g_scal[1];
    float w0n = sqrtf(g_scal[0]);
    float sG = fminf(0.02f * w0n / (sqrtf(g_scal[3 + b]) + 1e-8f), 1.0f);
    float s_prev = dw_scale(w0n, g_scal[5 + (((chunk - 1) & 1) << 1) + b]);
    float dk = decay * s_prev;
    float c = (1.0f - decay) * eta * sG;
    float4 g = ((const float4*)g_G)[base];
    float4 dw = ((const float4*)g_dW)[base];
    float4 nd = make_float4(dk * dw.x + c * g.x, dk * dw.y + c * g.y,
                            dk * dw.z + c * g.z, dk * dw.w + c * g.w);
    ((float4*)g_dW)[base] = nd;
    float ss = nd.x * nd.x + nd.y * nd.y + nd.z * nd.z + nd.w * nd.w;
    ss = blockSum(ss);
    if (threadIdx.x == 0) atomicAdd(&g_scal[5 + ((chunk & 1) << 1) + b], ss);
}

// ---------------------------------------------------------------- final projected dW write
__global__ void k_final(float* __restrict__ dst) {
    int b = blockIdx.y;
    size_t base = (size_t)b * (DM * DI / 4) + (size_t)blockIdx.x * 256 + threadIdx.x;
    float w0n = sqrtf(g_scal[0]);
    float s = dw_scale(w0n, g_scal[5 + (((NCHUNK - 1) & 1) << 1) + b]);
    float4 v = ((const float4*)g_dW)[base];
    ((float4*)dst)[base] = make_float4(v.x * s, v.y * s, v.z * s, v.w * s);
}

// ---------------------------------------------------------------- launch
extern "C" void kernel_launch(void* const* d_in, const int* in_sizes, int n_in,
                              void* d_out, int out_size) {
    const float* z = (const float*)d_in[0];
    const float* src = (const float*)d_in[1];
    const float* W0 = (const float*)d_in[2];
    const float* bias = (const float*)d_in[3];
    const float* cw = (const float*)d_in[4];
    const float* lil = (const float*)d_in[5];
    const float* ldl = (const float*)d_in[6];
    float* out = (float*)d_out;

    k_init<<<2048, 256>>>();
    k_prep<<<2048, 256>>>(W0, lil, ldl);
    k_vu<<<BB * TT, 256>>>(src, cw);
    k_zu<<<BB * TT, 256>>>(z);

    dim3 gO(CCHUNK / 128, DM / 128, BB * SPLITK);  // 2 x 8 x 16 = 256 blocks
    dim3 gG(DM / 128, DI / 128, BB);               // 8 x 16 x 2 = 256 blocks
    dim3 gE(2048, BB);
    int nComb = BB * CCHUNK * DM / 4 / 256;  // 512 blocks

    for (int c = 0; c < NCHUNK; c++) {
        k_gemmO<<<gO, 256>>>(z, W0, c);
        k_combine<<<nComb, 256>>>(bias, out, c);
        k_gemmG<<<gG, 256>>>(c);
        k_update<<<gE, 256>>>(c);
    }

    if (out_size >= BB * TT * DM + BB * DM * DI) {
        float* dwout = out + (size_t)BB * TT * DM;
        k_final<<<gE, 256>>>(dwout);
    }
}